// round 2
// baseline (speedup 1.0000x reference)
#include <cuda_runtime.h>
#include <math.h>

#define V      50000
#define B      512
#define KT     200
#define ALPHA  20.0f
#define THRESH 0.005f
#define VT     64
#define TB     128
#define GV     37
#define NTILES 782   // ceil(50000/64)

// ---- device scratch (no allocs allowed) ----
__device__ float g_K  [(size_t)V * KT];   // K transposed  [v][k]
__device__ float g_KM [(size_t)V * KT];   // K*M transposed [v][k]
__device__ float g_bow[(size_t)V * B];    // softmax(bow)^T [v][b]
__device__ float g_v  [(size_t)V * B];    // committed v    [v][b]
__device__ float g_u  [KT * B];           // u [k][b]
__device__ float g_t  [KT * B];           // accumulator [k][b]
__device__ float g_rowmax[B];
__device__ float g_rowinv[B];
__device__ float g_errb[B];
__device__ int   g_done;

// ---- f32x2 helpers ----
__device__ __forceinline__ unsigned long long pk(float a, float b) {
    unsigned long long r;
    asm("mov.b64 %0, {%1, %2};" : "=l"(r) : "f"(a), "f"(b));
    return r;
}
__device__ __forceinline__ unsigned long long ffma2(unsigned long long a,
                                                    unsigned long long b,
                                                    unsigned long long c) {
    unsigned long long d;
    asm("fma.rn.f32x2 %0, %1, %2, %3;" : "=l"(d) : "l"(a), "l"(b), "l"(c));
    return d;
}
__device__ __forceinline__ float2 upk(unsigned long long v) {
    float2 r;
    asm("mov.b64 {%0, %1}, %2;" : "=f"(r.x), "=f"(r.y) : "l"(v));
    return r;
}

// ---- init ----
__global__ void initK() {
    int idx = blockIdx.x * 256 + threadIdx.x;
    if (idx < KT * B) { g_u[idx] = 1.0f / (float)KT; g_t[idx] = 0.0f; }
    if (idx < B) g_errb[idx] = 0.0f;
    if (idx == 0) g_done = 0;
}

// ---- softmax row stats over bow rows ----
__global__ void rowstats(const float* __restrict__ bow) {
    int b = blockIdx.x;
    const float* row = bow + (size_t)b * V;
    __shared__ float red[256];
    int tid = threadIdx.x;
    float m = -1e30f;
    for (int v = tid; v < V; v += 256) m = fmaxf(m, row[v]);
    red[tid] = m; __syncthreads();
    for (int s = 128; s; s >>= 1) { if (tid < s) red[tid] = fmaxf(red[tid], red[tid + s]); __syncthreads(); }
    m = red[0]; __syncthreads();
    float sum = 0.0f;
    for (int v = tid; v < V; v += 256) sum += expf(row[v] - m);
    red[tid] = sum; __syncthreads();
    for (int s = 128; s; s >>= 1) { if (tid < s) red[tid] += red[tid + s]; __syncthreads(); }
    if (tid == 0) { g_rowmax[b] = m; g_rowinv[b] = 1.0f / red[0]; }
}

// ---- softmax + transpose: bow (B,V) -> g_bow (V,B) ----
__global__ void bowT(const float* __restrict__ bow) {
    __shared__ float tile[32][33];
    int v0 = blockIdx.x * 32, b0 = blockIdx.y * 32;
    int v = v0 + threadIdx.x, b = b0 + threadIdx.y;
    float val = 0.0f;
    if (v < V) val = expf(bow[(size_t)b * V + v] - g_rowmax[b]) * g_rowinv[b];
    tile[threadIdx.y][threadIdx.x] = val;
    __syncthreads();
    int vo = v0 + threadIdx.y, bo = b0 + threadIdx.x;
    if (vo < V) g_bow[(size_t)vo * B + bo] = tile[threadIdx.x][threadIdx.y];
}

// ---- K / K*M precompute, transposed to [v][k] ----
__global__ void kprep(const float* __restrict__ beta) {
    __shared__ float tk[32][33], tkm[32][33];
    int v0 = blockIdx.x * 32, k0 = blockIdx.y * 32;
    int v = v0 + threadIdx.x, k = k0 + threadIdx.y;
    float Kv = 0.0f, KMv = 0.0f;
    if (v < V && k < KT) {
        float M = 1.0f - beta[(size_t)k * V + v];
        Kv = expf(-ALPHA * M);
        KMv = Kv * M;
    }
    tk[threadIdx.y][threadIdx.x] = Kv;
    tkm[threadIdx.y][threadIdx.x] = KMv;
    __syncthreads();
    int vo = v0 + threadIdx.y, ko = k0 + threadIdx.x;
    if (vo < V && ko < KT) {
        g_K [(size_t)vo * KT + ko] = tk [threadIdx.x][threadIdx.y];
        g_KM[(size_t)vo * KT + ko] = tkm[threadIdx.x][threadIdx.y];
    }
}

// ---- fused iteration: g_t += K @ (bow_t / (K^T u)); optional write of vv to g_v ----
__global__ __launch_bounds__(256) void iterK(int writeV) {
    if (g_done) return;
    extern __shared__ float sh[];
    float* u_s  = sh;                      // KT*TB
    float* K_s  = sh + KT * TB;            // VT*KT
    float* vv_s = sh + KT * TB + VT * KT;  // VT*TB
    const int t = threadIdx.x, tb = t & 31, wid = t >> 5;
    const int b0 = blockIdx.y * TB;

    for (int e = t; e < (KT * TB) / 4; e += 256) {
        int k = e >> 5, b4 = e & 31;
        *(float4*)&u_s[k * TB + b4 * 4] = *(const float4*)&g_u[k * B + b0 + b4 * 4];
    }
    unsigned long long tacc[50];
#pragma unroll
    for (int i = 0; i < 50; i++) tacc[i] = 0ULL;
    __syncthreads();

    for (int tile = blockIdx.x; tile < NTILES; tile += GV) {
        const int v0 = tile * VT;
        for (int e = t; e < (VT * KT) / 4; e += 256) {
            int vi = e / 50, k4 = e - vi * 50;
            float4 val = make_float4(0.f, 0.f, 0.f, 0.f);
            if (v0 + vi < V) val = *(const float4*)&g_K[(size_t)(v0 + vi) * KT + k4 * 4];
            *(float4*)&K_s[vi * KT + k4 * 4] = val;
        }
        __syncthreads();

        // phase A: s = K^T u for 8 v-rows per warp, 4 b-cols per thread
        unsigned long long sA[16];
#pragma unroll
        for (int i = 0; i < 16; i++) sA[i] = 0ULL;
        const float* Krow = &K_s[(wid * 8) * KT];
        for (int k = 0; k < KT; k++) {
            float4 uu = *(float4*)&u_s[k * TB + tb * 4];
            unsigned long long u01 = pk(uu.x, uu.y), u23 = pk(uu.z, uu.w);
#pragma unroll
            for (int i = 0; i < 8; i++) {
                float kv = Krow[i * KT + k];
                unsigned long long kk = pk(kv, kv);
                sA[2 * i]     = ffma2(kk, u01, sA[2 * i]);
                sA[2 * i + 1] = ffma2(kk, u23, sA[2 * i + 1]);
            }
        }
        // phase A2: vv = bow / s
#pragma unroll
        for (int i = 0; i < 8; i++) {
            int v = v0 + wid * 8 + i;
            float4 vv = make_float4(0.f, 0.f, 0.f, 0.f);
            if (v < V) {
                float2 s01 = upk(sA[2 * i]), s23 = upk(sA[2 * i + 1]);
                float4 bw = *(const float4*)&g_bow[(size_t)v * B + b0 + tb * 4];
                vv.x = bw.x / s01.x; vv.y = bw.y / s01.y;
                vv.z = bw.z / s23.x; vv.w = bw.w / s23.y;
                if (writeV) *(float4*)&g_v[(size_t)v * B + b0 + tb * 4] = vv;
            }
            *(float4*)&vv_s[(wid * 8 + i) * TB + tb * 4] = vv;
        }
        __syncthreads();

        // phase B: t += K @ vv  (register accumulation, 25 k-rows per thread)
        for (int v = 0; v < VT; v++) {
            float4 vvv = *(float4*)&vv_s[v * TB + tb * 4];
            unsigned long long v01 = pk(vvv.x, vvv.y), v23 = pk(vvv.z, vvv.w);
            const float* Kr = &K_s[v * KT + wid];
#pragma unroll
            for (int i = 0; i < 25; i++) {
                float kv = Kr[i * 8];
                unsigned long long kk = pk(kv, kv);
                tacc[2 * i]     = ffma2(kk, v01, tacc[2 * i]);
                tacc[2 * i + 1] = ffma2(kk, v23, tacc[2 * i + 1]);
            }
        }
        __syncthreads();
    }
#pragma unroll
    for (int i = 0; i < 25; i++) {
        int k = wid + 8 * i;
        float2 a = upk(tacc[2 * i]), b = upk(tacc[2 * i + 1]);
        float* dst = &g_t[k * B + b0 + tb * 4];
        atomicAdd(dst + 0, a.x); atomicAdd(dst + 1, a.y);
        atomicAdd(dst + 2, b.x); atomicAdd(dst + 3, b.y);
    }
}

// ---- u update: u = theta^T / t ; reset t ----
__global__ void uUpd(const float* __restrict__ theta) {
    if (g_done) return;
    int idx = blockIdx.x * 256 + threadIdx.x;
    int k = idx >> 9, b = idx & 511;
    g_u[idx] = theta[b * KT + k] / g_t[idx];
    g_t[idx] = 0.0f;
}

// ---- convergence error: errb[b] += sum_v |vn*(K^T un2) - bow| ----
__global__ __launch_bounds__(256) void errK() {
    if (g_done) return;
    extern __shared__ float sh[];
    float* u_s = sh;
    float* K_s = sh + KT * TB;
    const int t = threadIdx.x, tb = t & 31, wid = t >> 5;
    const int b0 = blockIdx.y * TB;
    for (int e = t; e < (KT * TB) / 4; e += 256) {
        int k = e >> 5, b4 = e & 31;
        *(float4*)&u_s[k * TB + b4 * 4] = *(const float4*)&g_u[k * B + b0 + b4 * 4];
    }
    float e0 = 0.f, e1 = 0.f, e2 = 0.f, e3 = 0.f;
    __syncthreads();
    for (int tile = blockIdx.x; tile < NTILES; tile += GV) {
        const int v0 = tile * VT;
        for (int e = t; e < (VT * KT) / 4; e += 256) {
            int vi = e / 50, k4 = e - vi * 50;
            float4 val = make_float4(0.f, 0.f, 0.f, 0.f);
            if (v0 + vi < V) val = *(const float4*)&g_K[(size_t)(v0 + vi) * KT + k4 * 4];
            *(float4*)&K_s[vi * KT + k4 * 4] = val;
        }
        __syncthreads();
        unsigned long long sA[16];
#pragma unroll
        for (int i = 0; i < 16; i++) sA[i] = 0ULL;
        const float* Krow = &K_s[(wid * 8) * KT];
        for (int k = 0; k < KT; k++) {
            float4 uu = *(float4*)&u_s[k * TB + tb * 4];
            unsigned long long u01 = pk(uu.x, uu.y), u23 = pk(uu.z, uu.w);
#pragma unroll
            for (int i = 0; i < 8; i++) {
                float kv = Krow[i * KT + k];
                unsigned long long kk = pk(kv, kv);
                sA[2 * i]     = ffma2(kk, u01, sA[2 * i]);
                sA[2 * i + 1] = ffma2(kk, u23, sA[2 * i + 1]);
            }
        }
#pragma unroll
        for (int i = 0; i < 8; i++) {
            int v = v0 + wid * 8 + i;
            if (v < V) {
                float2 s01 = upk(sA[2 * i]), s23 = upk(sA[2 * i + 1]);
                float4 vn = *(const float4*)&g_v  [(size_t)v * B + b0 + tb * 4];
                float4 bw = *(const float4*)&g_bow[(size_t)v * B + b0 + tb * 4];
                e0 += fabsf(vn.x * s01.x - bw.x);
                e1 += fabsf(vn.y * s01.y - bw.y);
                e2 += fabsf(vn.z * s23.x - bw.z);
                e3 += fabsf(vn.w * s23.y - bw.w);
            }
        }
        __syncthreads();
    }
    atomicAdd(&g_errb[b0 + tb * 4 + 0], e0);
    atomicAdd(&g_errb[b0 + tb * 4 + 1], e1);
    atomicAdd(&g_errb[b0 + tb * 4 + 2], e2);
    atomicAdd(&g_errb[b0 + tb * 4 + 3], e3);
}

// ---- done flag update ----
__global__ void doneK() {
    if (g_done) return;
    __shared__ float red[512];
    int t = threadIdx.x;
    red[t] = g_errb[t];
    __syncthreads();
    for (int s = 256; s; s >>= 1) { if (t < s) red[t] = fmaxf(red[t], red[t + s]); __syncthreads(); }
    g_errb[t] = 0.0f;
    if (t == 0 && red[0] <= THRESH) g_done = 1;
}

// ---- final: g_t += (K*M) @ v ----
__global__ __launch_bounds__(256) void finK() {
    extern __shared__ float sh[];
    float* K_s = sh;
    const int t = threadIdx.x, tb = t & 31, wid = t >> 5;
    const int b0 = blockIdx.y * TB;
    unsigned long long tacc[50];
#pragma unroll
    for (int i = 0; i < 50; i++) tacc[i] = 0ULL;
    for (int tile = blockIdx.x; tile < NTILES; tile += GV) {
        const int v0 = tile * VT;
        for (int e = t; e < (VT * KT) / 4; e += 256) {
            int vi = e / 50, k4 = e - vi * 50;
            float4 val = make_float4(0.f, 0.f, 0.f, 0.f);
            if (v0 + vi < V) val = *(const float4*)&g_KM[(size_t)(v0 + vi) * KT + k4 * 4];
            *(float4*)&K_s[vi * KT + k4 * 4] = val;
        }
        __syncthreads();
        for (int v = 0; v < VT; v++) {
            int vg = v0 + v;
            float4 vv = make_float4(0.f, 0.f, 0.f, 0.f);
            if (vg < V) vv = *(const float4*)&g_v[(size_t)vg * B + b0 + tb * 4];
            unsigned long long v01 = pk(vv.x, vv.y), v23 = pk(vv.z, vv.w);
            const float* Kr = &K_s[v * KT + wid];
#pragma unroll
            for (int i = 0; i < 25; i++) {
                float kv = Kr[i * 8];
                unsigned long long kk = pk(kv, kv);
                tacc[2 * i]     = ffma2(kk, v01, tacc[2 * i]);
                tacc[2 * i + 1] = ffma2(kk, v23, tacc[2 * i + 1]);
            }
        }
        __syncthreads();
    }
#pragma unroll
    for (int i = 0; i < 25; i++) {
        int k = wid + 8 * i;
        float2 a = upk(tacc[2 * i]), b = upk(tacc[2 * i + 1]);
        float* dst = &g_t[k * B + b0 + tb * 4];
        atomicAdd(dst + 0, a.x); atomicAdd(dst + 1, a.y);
        atomicAdd(dst + 2, b.x); atomicAdd(dst + 3, b.y);
    }
}

// ---- output: mean_b sum_k u*t ----
__global__ void divRed(float* __restrict__ out) {
    __shared__ float red[1024];
    int t = threadIdx.x;
    float s = 0.0f;
    for (int i = t; i < KT * B; i += 1024) s += g_u[i] * g_t[i];
    red[t] = s;
    __syncthreads();
    for (int st = 512; st; st >>= 1) { if (t < st) red[t] += red[t + st]; __syncthreads(); }
    if (t == 0) out[0] = red[0] / (float)B;
}

#define ITER_SMEM ((KT*TB + VT*KT + VT*TB) * 4)   // 186368
#define ERR_SMEM  ((KT*TB + VT*KT) * 4)           // 153600
#define FIN_SMEM  ((VT*KT) * 4)                   // 51200

extern "C" void kernel_launch(void* const* d_in, const int* in_sizes, int n_in,
                              void* d_out, int out_size) {
    const float* beta  = (const float*)d_in[0];
    const float* theta = (const float*)d_in[1];
    const float* bow   = (const float*)d_in[2];
    float* out = (float*)d_out;

    cudaFuncSetAttribute(iterK, cudaFuncAttributeMaxDynamicSharedMemorySize, ITER_SMEM);
    cudaFuncSetAttribute(errK,  cudaFuncAttributeMaxDynamicSharedMemorySize, ERR_SMEM);
    cudaFuncSetAttribute(finK,  cudaFuncAttributeMaxDynamicSharedMemorySize, FIN_SMEM);

    initK<<<400, 256>>>();
    rowstats<<<512, 256>>>(bow);
    bowT<<<dim3(1563, 16), dim3(32, 32)>>>(bow);
    kprep<<<dim3(1563, 7), dim3(32, 32)>>>(beta);

    for (int blk = 0; blk < 5; blk++) {
        for (int it = 0; it < 20; it++) {
            iterK<<<dim3(GV, 4), 256, ITER_SMEM>>>(0);
            uUpd<<<400, 256>>>(theta);
        }
        iterK<<<dim3(GV, 4), 256, ITER_SMEM>>>(1);   // writes vn -> g_v
        uUpd<<<400, 256>>>(theta);                   // u -> un2
        errK<<<dim3(GV, 4), 256, ERR_SMEM>>>();
        doneK<<<1, 512>>>();
    }
    finK<<<dim3(GV, 4), 256, FIN_SMEM>>>();
    divRed<<<1, 1024>>>(out);
}

// round 3
// speedup vs baseline: 1.0000x; 1.0000x over previous
#include <cuda_runtime.h>
#include <math.h>

#define V      50000
#define B      512
#define KT     200
#define ALPHA  20.0f
#define THRESH 0.005f
#define VT     64
#define TB     128
#define GV     37
#define NTILES 782   // ceil(50000/64)

// ---- device scratch (no allocs allowed) ----
__device__ float g_K  [(size_t)V * KT];   // K transposed  [v][k]
__device__ float g_KM [(size_t)V * KT];   // K*M transposed [v][k]
__device__ float g_bow[(size_t)V * B];    // softmax(bow)^T [v][b]
__device__ float g_v  [(size_t)V * B];    // committed v    [v][b]
__device__ float g_u  [KT * B];           // u [k][b]
__device__ float g_t  [KT * B];           // accumulator [k][b]
__device__ float g_rowmax[B];
__device__ float g_rowinv[B];
__device__ float g_errb[B];
__device__ int   g_done;

// ---- f32x2 helpers ----
__device__ __forceinline__ unsigned long long pk(float a, float b) {
    unsigned long long r;
    asm("mov.b64 %0, {%1, %2};" : "=l"(r) : "f"(a), "f"(b));
    return r;
}
__device__ __forceinline__ unsigned long long ffma2(unsigned long long a,
                                                    unsigned long long b,
                                                    unsigned long long c) {
    unsigned long long d;
    asm("fma.rn.f32x2 %0, %1, %2, %3;" : "=l"(d) : "l"(a), "l"(b), "l"(c));
    return d;
}
__device__ __forceinline__ float2 upk(unsigned long long v) {
    float2 r;
    asm("mov.b64 {%0, %1}, %2;" : "=f"(r.x), "=f"(r.y) : "l"(v));
    return r;
}

// ---- init ----
__global__ void initK() {
    int idx = blockIdx.x * 256 + threadIdx.x;
    if (idx < KT * B) { g_u[idx] = 1.0f / (float)KT; g_t[idx] = 0.0f; }
    if (idx < B) g_errb[idx] = 0.0f;
    if (idx == 0) g_done = 0;
}

// ---- softmax row stats over bow rows ----
__global__ void rowstats(const float* __restrict__ bow) {
    int b = blockIdx.x;
    const float* row = bow + (size_t)b * V;
    __shared__ float red[256];
    int tid = threadIdx.x;
    float m = -1e30f;
    for (int v = tid; v < V; v += 256) m = fmaxf(m, row[v]);
    red[tid] = m; __syncthreads();
    for (int s = 128; s; s >>= 1) { if (tid < s) red[tid] = fmaxf(red[tid], red[tid + s]); __syncthreads(); }
    m = red[0]; __syncthreads();
    float sum = 0.0f;
    for (int v = tid; v < V; v += 256) sum += expf(row[v] - m);
    red[tid] = sum; __syncthreads();
    for (int s = 128; s; s >>= 1) { if (tid < s) red[tid] += red[tid + s]; __syncthreads(); }
    if (tid == 0) { g_rowmax[b] = m; g_rowinv[b] = 1.0f / red[0]; }
}

// ---- softmax + transpose: bow (B,V) -> g_bow (V,B) ----
__global__ void bowT(const float* __restrict__ bow) {
    __shared__ float tile[32][33];
    int v0 = blockIdx.x * 32, b0 = blockIdx.y * 32;
    int v = v0 + threadIdx.x, b = b0 + threadIdx.y;
    float val = 0.0f;
    if (v < V) val = expf(bow[(size_t)b * V + v] - g_rowmax[b]) * g_rowinv[b];
    tile[threadIdx.y][threadIdx.x] = val;
    __syncthreads();
    int vo = v0 + threadIdx.y, bo = b0 + threadIdx.x;
    if (vo < V) g_bow[(size_t)vo * B + bo] = tile[threadIdx.x][threadIdx.y];
}

// ---- K / K*M precompute, transposed to [v][k] ----
__global__ void kprep(const float* __restrict__ beta) {
    __shared__ float tk[32][33], tkm[32][33];
    int v0 = blockIdx.x * 32, k0 = blockIdx.y * 32;
    int v = v0 + threadIdx.x, k = k0 + threadIdx.y;
    float Kv = 0.0f, KMv = 0.0f;
    if (v < V && k < KT) {
        float M = 1.0f - beta[(size_t)k * V + v];
        Kv = expf(-ALPHA * M);
        KMv = Kv * M;
    }
    tk[threadIdx.y][threadIdx.x] = Kv;
    tkm[threadIdx.y][threadIdx.x] = KMv;
    __syncthreads();
    int vo = v0 + threadIdx.y, ko = k0 + threadIdx.x;
    if (vo < V && ko < KT) {
        g_K [(size_t)vo * KT + ko] = tk [threadIdx.x][threadIdx.y];
        g_KM[(size_t)vo * KT + ko] = tkm[threadIdx.x][threadIdx.y];
    }
}

// ---- fused iteration: g_t += K @ (bow_t / (K^T u)); optional write of vv to g_v ----
__global__ __launch_bounds__(256) void iterK(int writeV) {
    if (g_done) return;
    extern __shared__ float sh[];
    float* u_s  = sh;                      // KT*TB
    float* K_s  = sh + KT * TB;            // VT*KT
    float* vv_s = sh + KT * TB + VT * KT;  // VT*TB
    const int t = threadIdx.x, tb = t & 31, wid = t >> 5;
    const int b0 = blockIdx.y * TB;

    for (int e = t; e < (KT * TB) / 4; e += 256) {
        int k = e >> 5, b4 = e & 31;
        *(float4*)&u_s[k * TB + b4 * 4] = *(const float4*)&g_u[k * B + b0 + b4 * 4];
    }
    unsigned long long tacc[50];
#pragma unroll
    for (int i = 0; i < 50; i++) tacc[i] = 0ULL;
    __syncthreads();

    for (int tile = blockIdx.x; tile < NTILES; tile += GV) {
        const int v0 = tile * VT;
        for (int e = t; e < (VT * KT) / 4; e += 256) {
            int vi = e / 50, k4 = e - vi * 50;
            float4 val = make_float4(0.f, 0.f, 0.f, 0.f);
            if (v0 + vi < V) val = *(const float4*)&g_K[(size_t)(v0 + vi) * KT + k4 * 4];
            *(float4*)&K_s[vi * KT + k4 * 4] = val;
        }
        __syncthreads();

        // phase A: s = K^T u for 8 v-rows per warp, 4 b-cols per thread
        unsigned long long sA[16];
#pragma unroll
        for (int i = 0; i < 16; i++) sA[i] = 0ULL;
        const float* Krow = &K_s[(wid * 8) * KT];
        for (int k = 0; k < KT; k++) {
            float4 uu = *(float4*)&u_s[k * TB + tb * 4];
            unsigned long long u01 = pk(uu.x, uu.y), u23 = pk(uu.z, uu.w);
#pragma unroll
            for (int i = 0; i < 8; i++) {
                float kv = Krow[i * KT + k];
                unsigned long long kk = pk(kv, kv);
                sA[2 * i]     = ffma2(kk, u01, sA[2 * i]);
                sA[2 * i + 1] = ffma2(kk, u23, sA[2 * i + 1]);
            }
        }
        // phase A2: vv = bow / s
#pragma unroll
        for (int i = 0; i < 8; i++) {
            int v = v0 + wid * 8 + i;
            float4 vv = make_float4(0.f, 0.f, 0.f, 0.f);
            if (v < V) {
                float2 s01 = upk(sA[2 * i]), s23 = upk(sA[2 * i + 1]);
                float4 bw = *(const float4*)&g_bow[(size_t)v * B + b0 + tb * 4];
                vv.x = bw.x / s01.x; vv.y = bw.y / s01.y;
                vv.z = bw.z / s23.x; vv.w = bw.w / s23.y;
                if (writeV) *(float4*)&g_v[(size_t)v * B + b0 + tb * 4] = vv;
            }
            *(float4*)&vv_s[(wid * 8 + i) * TB + tb * 4] = vv;
        }
        __syncthreads();

        // phase B: t += K @ vv  (register accumulation, 25 k-rows per thread)
        for (int v = 0; v < VT; v++) {
            float4 vvv = *(float4*)&vv_s[v * TB + tb * 4];
            unsigned long long v01 = pk(vvv.x, vvv.y), v23 = pk(vvv.z, vvv.w);
            const float* Kr = &K_s[v * KT + wid];
#pragma unroll
            for (int i = 0; i < 25; i++) {
                float kv = Kr[i * 8];
                unsigned long long kk = pk(kv, kv);
                tacc[2 * i]     = ffma2(kk, v01, tacc[2 * i]);
                tacc[2 * i + 1] = ffma2(kk, v23, tacc[2 * i + 1]);
            }
        }
        __syncthreads();
    }
#pragma unroll
    for (int i = 0; i < 25; i++) {
        int k = wid + 8 * i;
        float2 a = upk(tacc[2 * i]), b = upk(tacc[2 * i + 1]);
        float* dst = &g_t[k * B + b0 + tb * 4];
        atomicAdd(dst + 0, a.x); atomicAdd(dst + 1, a.y);
        atomicAdd(dst + 2, b.x); atomicAdd(dst + 3, b.y);
    }
}

// ---- u update: u = theta^T / t ; reset t ----
__global__ void uUpd(const float* __restrict__ theta) {
    if (g_done) return;
    int idx = blockIdx.x * 256 + threadIdx.x;
    int k = idx >> 9, b = idx & 511;
    g_u[idx] = theta[b * KT + k] / g_t[idx];
    g_t[idx] = 0.0f;
}

// ---- convergence error: errb[b] += sum_v |vn*(K^T un2) - bow| ----
__global__ __launch_bounds__(256) void errK() {
    if (g_done) return;
    extern __shared__ float sh[];
    float* u_s = sh;
    float* K_s = sh + KT * TB;
    const int t = threadIdx.x, tb = t & 31, wid = t >> 5;
    const int b0 = blockIdx.y * TB;
    for (int e = t; e < (KT * TB) / 4; e += 256) {
        int k = e >> 5, b4 = e & 31;
        *(float4*)&u_s[k * TB + b4 * 4] = *(const float4*)&g_u[k * B + b0 + b4 * 4];
    }
    float e0 = 0.f, e1 = 0.f, e2 = 0.f, e3 = 0.f;
    __syncthreads();
    for (int tile = blockIdx.x; tile < NTILES; tile += GV) {
        const int v0 = tile * VT;
        for (int e = t; e < (VT * KT) / 4; e += 256) {
            int vi = e / 50, k4 = e - vi * 50;
            float4 val = make_float4(0.f, 0.f, 0.f, 0.f);
            if (v0 + vi < V) val = *(const float4*)&g_K[(size_t)(v0 + vi) * KT + k4 * 4];
            *(float4*)&K_s[vi * KT + k4 * 4] = val;
        }
        __syncthreads();
        unsigned long long sA[16];
#pragma unroll
        for (int i = 0; i < 16; i++) sA[i] = 0ULL;
        const float* Krow = &K_s[(wid * 8) * KT];
        for (int k = 0; k < KT; k++) {
            float4 uu = *(float4*)&u_s[k * TB + tb * 4];
            unsigned long long u01 = pk(uu.x, uu.y), u23 = pk(uu.z, uu.w);
#pragma unroll
            for (int i = 0; i < 8; i++) {
                float kv = Krow[i * KT + k];
                unsigned long long kk = pk(kv, kv);
                sA[2 * i]     = ffma2(kk, u01, sA[2 * i]);
                sA[2 * i + 1] = ffma2(kk, u23, sA[2 * i + 1]);
            }
        }
#pragma unroll
        for (int i = 0; i < 8; i++) {
            int v = v0 + wid * 8 + i;
            if (v < V) {
                float2 s01 = upk(sA[2 * i]), s23 = upk(sA[2 * i + 1]);
                float4 vn = *(const float4*)&g_v  [(size_t)v * B + b0 + tb * 4];
                float4 bw = *(const float4*)&g_bow[(size_t)v * B + b0 + tb * 4];
                e0 += fabsf(vn.x * s01.x - bw.x);
                e1 += fabsf(vn.y * s01.y - bw.y);
                e2 += fabsf(vn.z * s23.x - bw.z);
                e3 += fabsf(vn.w * s23.y - bw.w);
            }
        }
        __syncthreads();
    }
    atomicAdd(&g_errb[b0 + tb * 4 + 0], e0);
    atomicAdd(&g_errb[b0 + tb * 4 + 1], e1);
    atomicAdd(&g_errb[b0 + tb * 4 + 2], e2);
    atomicAdd(&g_errb[b0 + tb * 4 + 3], e3);
}

// ---- done flag update ----
__global__ void doneK() {
    if (g_done) return;
    __shared__ float red[512];
    int t = threadIdx.x;
    red[t] = g_errb[t];
    __syncthreads();
    for (int s = 256; s; s >>= 1) { if (t < s) red[t] = fmaxf(red[t], red[t + s]); __syncthreads(); }
    g_errb[t] = 0.0f;
    if (t == 0 && red[0] <= THRESH) g_done = 1;
}

// ---- final: g_t += (K*M) @ v ----
__global__ __launch_bounds__(256) void finK() {
    extern __shared__ float sh[];
    float* K_s = sh;
    const int t = threadIdx.x, tb = t & 31, wid = t >> 5;
    const int b0 = blockIdx.y * TB;
    unsigned long long tacc[50];
#pragma unroll
    for (int i = 0; i < 50; i++) tacc[i] = 0ULL;
    for (int tile = blockIdx.x; tile < NTILES; tile += GV) {
        const int v0 = tile * VT;
        for (int e = t; e < (VT * KT) / 4; e += 256) {
            int vi = e / 50, k4 = e - vi * 50;
            float4 val = make_float4(0.f, 0.f, 0.f, 0.f);
            if (v0 + vi < V) val = *(const float4*)&g_KM[(size_t)(v0 + vi) * KT + k4 * 4];
            *(float4*)&K_s[vi * KT + k4 * 4] = val;
        }
        __syncthreads();
        for (int v = 0; v < VT; v++) {
            int vg = v0 + v;
            float4 vv = make_float4(0.f, 0.f, 0.f, 0.f);
            if (vg < V) vv = *(const float4*)&g_v[(size_t)vg * B + b0 + tb * 4];
            unsigned long long v01 = pk(vv.x, vv.y), v23 = pk(vv.z, vv.w);
            const float* Kr = &K_s[v * KT + wid];
#pragma unroll
            for (int i = 0; i < 25; i++) {
                float kv = Kr[i * 8];
                unsigned long long kk = pk(kv, kv);
                tacc[2 * i]     = ffma2(kk, v01, tacc[2 * i]);
                tacc[2 * i + 1] = ffma2(kk, v23, tacc[2 * i + 1]);
            }
        }
        __syncthreads();
    }
#pragma unroll
    for (int i = 0; i < 25; i++) {
        int k = wid + 8 * i;
        float2 a = upk(tacc[2 * i]), b = upk(tacc[2 * i + 1]);
        float* dst = &g_t[k * B + b0 + tb * 4];
        atomicAdd(dst + 0, a.x); atomicAdd(dst + 1, a.y);
        atomicAdd(dst + 2, b.x); atomicAdd(dst + 3, b.y);
    }
}

// ---- output: mean_b sum_k u*t ----
__global__ void divRed(float* __restrict__ out) {
    __shared__ float red[1024];
    int t = threadIdx.x;
    float s = 0.0f;
    for (int i = t; i < KT * B; i += 1024) s += g_u[i] * g_t[i];
    red[t] = s;
    __syncthreads();
    for (int st = 512; st; st >>= 1) { if (t < st) red[t] += red[t + st]; __syncthreads(); }
    if (t == 0) out[0] = red[0] / (float)B;
}

#define ITER_SMEM ((KT*TB + VT*KT + VT*TB) * 4)   // 186368
#define ERR_SMEM  ((KT*TB + VT*KT) * 4)           // 153600
#define FIN_SMEM  ((VT*KT) * 4)                   // 51200

extern "C" void kernel_launch(void* const* d_in, const int* in_sizes, int n_in,
                              void* d_out, int out_size) {
    const float* beta  = (const float*)d_in[0];
    const float* theta = (const float*)d_in[1];
    const float* bow   = (const float*)d_in[2];
    float* out = (float*)d_out;

    cudaFuncSetAttribute(iterK, cudaFuncAttributeMaxDynamicSharedMemorySize, ITER_SMEM);
    cudaFuncSetAttribute(errK,  cudaFuncAttributeMaxDynamicSharedMemorySize, ERR_SMEM);
    cudaFuncSetAttribute(finK,  cudaFuncAttributeMaxDynamicSharedMemorySize, FIN_SMEM);

    initK<<<400, 256>>>();
    rowstats<<<512, 256>>>(bow);
    bowT<<<dim3(1563, 16), dim3(32, 32)>>>(bow);
    kprep<<<dim3(1563, 7), dim3(32, 32)>>>(beta);

    for (int blk = 0; blk < 5; blk++) {
        for (int it = 0; it < 20; it++) {
            iterK<<<dim3(GV, 4), 256, ITER_SMEM>>>(0);
            uUpd<<<400, 256>>>(theta);
        }
        iterK<<<dim3(GV, 4), 256, ITER_SMEM>>>(1);   // writes vn -> g_v
        uUpd<<<400, 256>>>(theta);                   // u -> un2
        errK<<<dim3(GV, 4), 256, ERR_SMEM>>>();
        doneK<<<1, 512>>>();
    }
    finK<<<dim3(GV, 4), 256, FIN_SMEM>>>();
    divRed<<<1, 1024>>>(out);
}

// round 4
// speedup vs baseline: 3.0161x; 3.0160x over previous
#include <cuda_runtime.h>
#include <cuda_bf16.h>
#include <math.h>

#define V 50000
#define BN 512
#define KT 200
#define KS 216
#define KP 208
#define VP 136
#define NT 391
#define GV 37
#define INV_C 4.8516519540979028e8f
#define C_NEG 2.0611536224385579e-9f
#define THRESH_H (0.005f*INV_C)

__device__ __align__(16) __nv_bfloat16 g_Evk[(size_t)V*KS];
__device__ __align__(16) __nv_bfloat16 g_Ekv[(size_t)KP*V];
__device__ __align__(16) __nv_bfloat16 g_Gkv[(size_t)KP*V];
__device__ __align__(16) __nv_bfloat16 g_vh [(size_t)BN*V];
__device__ __align__(16) float g_bow[(size_t)V*BN];
__device__ __align__(16) float g_v  [(size_t)V*BN];
__device__ __align__(16) __nv_bfloat16 g_ut[BN*KS];
__device__ __align__(16) float g_uf[KP*BN];
__device__ __align__(16) float g_t [KP*BN];
__device__ __align__(16) float g_tf[KP*BN];
__device__ float g_U[BN], g_W[BN], g_Wv[BN], g_errb[BN];
__device__ float g_rmax[BN], g_rinv[BN];
__device__ int g_done;

__device__ __forceinline__ unsigned s2u(const void* p){
    unsigned a;
    asm("{.reg .u64 t; cvta.to.shared.u64 t, %1; cvt.u32.u64 %0, t;}" : "=r"(a) : "l"(p));
    return a;
}
__device__ __forceinline__ void ldsm4(unsigned&a0,unsigned&a1,unsigned&a2,unsigned&a3,unsigned ad){
    asm volatile("ldmatrix.sync.aligned.m8n8.x4.shared.b16 {%0,%1,%2,%3},[%4];"
        : "=r"(a0),"=r"(a1),"=r"(a2),"=r"(a3) : "r"(ad));
}
__device__ __forceinline__ void ldsm2(unsigned&a0,unsigned&a1,unsigned ad){
    asm volatile("ldmatrix.sync.aligned.m8n8.x2.shared.b16 {%0,%1},[%2];"
        : "=r"(a0),"=r"(a1) : "r"(ad));
}
__device__ __forceinline__ void mmaf(float d[4],unsigned a0,unsigned a1,unsigned a2,unsigned a3,
                                     unsigned b0,unsigned b1){
    asm("mma.sync.aligned.m16n8k16.row.col.f32.bf16.bf16.f32 "
        "{%0,%1,%2,%3},{%4,%5,%6,%7},{%8,%9},{%0,%1,%2,%3};"
        : "+f"(d[0]),"+f"(d[1]),"+f"(d[2]),"+f"(d[3])
        : "r"(a0),"r"(a1),"r"(a2),"r"(a3),"r"(b0),"r"(b1));
}

__device__ __forceinline__ void cp_u(char* sm,int b0,int tid){
    const uint4* s=(const uint4*)g_ut; uint4* d=(uint4*)sm;
    for(int e=tid;e<128*27;e+=256){ int r=e/27,c=e-r*27; d[e]=s[(b0+r)*27+c]; }
}
__device__ __forceinline__ void cp_evk(char* sm,int v0,int tid){
    const uint4* s=(const uint4*)g_Evk; uint4* d=(uint4*)sm;
    uint4 z=make_uint4(0,0,0,0);
    for(int e=tid;e<128*27;e+=256){ int r=e/27,c=e-r*27;
        d[e]=(v0+r<V)? s[(size_t)(v0+r)*27+c] : z; }
}
__device__ __forceinline__ void cp_ekv(char* sm,const __nv_bfloat16* g,int v0,int tid){
    uint4 z=make_uint4(0,0,0,0);
    for(int e=tid;e<KP*16;e+=256){ int r=e>>4,c=e&15;
        uint4 val=(v0+c*8+8<=V)? *(const uint4*)((const char*)g+(size_t)r*(V*2)+(size_t)v0*2+c*16):z;
        *(uint4*)(sm+r*(VP*2)+c*16)=val; }
}
__device__ __forceinline__ void cp_vh(char* sm,int b0,int v0,int tid){
    uint4 z=make_uint4(0,0,0,0);
    for(int e=tid;e<128*16;e+=256){ int r=e>>4,c=e&15;
        uint4 val=(v0+c*8+8<=V)? *(const uint4*)((const char*)g_vh+(size_t)(b0+r)*(V*2)+(size_t)v0*2+c*16):z;
        *(uint4*)(sm+r*(VP*2)+c*16)=val; }
}

__device__ __forceinline__ void phA(const char* smE,const char* smU,int w,int lane,float d[16][4]){
    unsigned aA=s2u(smE)+(w*16+(lane&7)+((lane>>3)&1)*8)*432+(lane>>4)*16;
    unsigned bA=s2u(smU)+(lane&7)*432+((lane>>3)&1)*16;
    for(int ks=0;ks<13;ks++){
        unsigned a0,a1,a2,a3; ldsm4(a0,a1,a2,a3,aA+ks*32);
#pragma unroll
        for(int nt=0;nt<16;nt++){
            unsigned b0,b1; ldsm2(b0,b1,bA+nt*3456+ks*32);
            mmaf(d[nt],a0,a1,a2,a3,b0,b1);
        }
    }
}
__device__ __forceinline__ void phB(const char* smE,const char* smV,int w,int lane,float acc[13][2][4]){
    unsigned aB=s2u(smE)+((lane&7)+((lane>>3)&1)*8)*272+(lane>>4)*16;
    unsigned bB=s2u(smV)+(w*16+(lane&7))*272+((lane>>3)&1)*16;
    for(int ks=0;ks<8;ks++){
        unsigned b00,b01,b10,b11;
        ldsm2(b00,b01,bB+ks*32); ldsm2(b10,b11,bB+2176+ks*32);
#pragma unroll
        for(int m=0;m<13;m++){
            unsigned a0,a1,a2,a3; ldsm4(a0,a1,a2,a3,aB+m*4352+ks*32);
            mmaf(acc[m][0],a0,a1,a2,a3,b00,b01);
            mmaf(acc[m][1],a0,a1,a2,a3,b10,b11);
        }
    }
}

__global__ void initK(){
    int i=blockIdx.x*256+threadIdx.x;
    if(i<BN*KS) g_ut[i]=__float2bfloat16((i%KS)<KT?0.005f:0.f);
    if(i<KP*BN){ g_t[i]=0.f; g_tf[i]=0.f; g_uf[i]=0.005f; }
    if(i<BN){ g_U[i]=1.f; g_W[i]=0.f; g_Wv[i]=0.f; g_errb[i]=0.f; }
    if(i==0) g_done=0;
}

__global__ void rowstats(const float* __restrict__ bow){
    int b=blockIdx.x; const float* row=bow+(size_t)b*V;
    __shared__ float red[256]; int t=threadIdx.x;
    float m=-1e30f;
    for(int v=t;v<V;v+=256) m=fmaxf(m,row[v]);
    red[t]=m; __syncthreads();
    for(int s=128;s;s>>=1){ if(t<s) red[t]=fmaxf(red[t],red[t+s]); __syncthreads(); }
    m=red[0]; __syncthreads();
    float sum=0.f;
    for(int v=t;v<V;v+=256) sum+=expf(row[v]-m);
    red[t]=sum; __syncthreads();
    for(int s=128;s;s>>=1){ if(t<s) red[t]+=red[t+s]; __syncthreads(); }
    if(t==0){ g_rmax[b]=m; g_rinv[b]=1.f/red[0]; }
}

__global__ void bowT(const float* __restrict__ bow){
    __shared__ float tile[32][33];
    int v0=blockIdx.x*32,b0=blockIdx.y*32;
    int v=v0+threadIdx.x,b=b0+threadIdx.y;
    float val=0.f;
    if(v<V) val=expf(bow[(size_t)b*V+v]-g_rmax[b])*g_rinv[b]*INV_C;
    tile[threadIdx.y][threadIdx.x]=val;
    __syncthreads();
    int vo=v0+threadIdx.y,bo=b0+threadIdx.x;
    if(vo<V) g_bow[(size_t)vo*BN+bo]=tile[threadIdx.x][threadIdx.y];
}

__global__ void kprep1(const float* __restrict__ beta){
    size_t i=(size_t)blockIdx.x*256+threadIdx.x;
    if(i>=(size_t)KT*V) return;
    float b=beta[i];
    float E=expm1f(20.f*b);
    g_Ekv[i]=__float2bfloat16(E);
    g_Gkv[i]=__float2bfloat16(E-b*(1.f+E));
}

__global__ void kprep2(const float* __restrict__ beta){
    __shared__ float t[32][33];
    int v0=blockIdx.x*32,k0=blockIdx.y*32;
    int v=v0+threadIdx.x,k=k0+threadIdx.y;
    float E=0.f;
    if(v<V&&k<KT) E=expm1f(20.f*beta[(size_t)k*V+v]);
    t[threadIdx.y][threadIdx.x]=E;
    __syncthreads();
    int vo=v0+threadIdx.y,ko=k0+threadIdx.x;
    if(vo<V&&ko<KT) g_Evk[(size_t)vo*KS+ko]=__float2bfloat16(t[threadIdx.x][threadIdx.y]);
}

__global__ __launch_bounds__(256) void iterK(int writeV){
    if(g_done) return;
    extern __shared__ char sm[];
    char* sU=sm; char* sE=sm+55296; char* sV=sm+111872;
    float* W_s=(float*)(sm+146688); float* U_s=(float*)(sm+147200);
    int tid=threadIdx.x,lane=tid&31,w=tid>>5,g=lane>>2,tg=lane&3;
    int b0=blockIdx.y*128;
    cp_u(sU,b0,tid);
    if(tid<128){ U_s[tid]=g_U[b0+tid]; W_s[tid]=0.f; }
    float acc[13][2][4];
#pragma unroll
    for(int m=0;m<13;m++) for(int p=0;p<2;p++) for(int q=0;q<4;q++) acc[m][p][q]=0.f;
    for(int t=blockIdx.x;t<NT;t+=GV){
        int v0=t*128;
        __syncthreads();
        cp_evk(sE,v0,tid);
        __syncthreads();
        float d[16][4];
#pragma unroll
        for(int nt=0;nt<16;nt++) for(int q=0;q<4;q++) d[nt][q]=0.f;
        phA(sE,sU,w,lane,d);
        int vr0=v0+w*16+g,vr1=vr0+8,rl0=w*16+g,rl1=rl0+8;
        __nv_bfloat16* vb=(__nv_bfloat16*)sV;
#pragma unroll
        for(int nt=0;nt<16;nt++){
            int c0=nt*8+2*tg;
            float Ua=U_s[c0],Ub=U_s[c0+1];
            float2 bw0=make_float2(0.f,0.f),bw1=make_float2(0.f,0.f);
            if(vr0<V) bw0=*(const float2*)&g_bow[(size_t)vr0*BN+b0+c0];
            if(vr1<V) bw1=*(const float2*)&g_bow[(size_t)vr1*BN+b0+c0];
            float v00=__fdividef(bw0.x,Ua+d[nt][0]);
            float v01=__fdividef(bw0.y,Ub+d[nt][1]);
            float v10=__fdividef(bw1.x,Ua+d[nt][2]);
            float v11=__fdividef(bw1.y,Ub+d[nt][3]);
            vb[c0*VP+rl0]=__float2bfloat16(v00);
            vb[(c0+1)*VP+rl0]=__float2bfloat16(v01);
            vb[c0*VP+rl1]=__float2bfloat16(v10);
            vb[(c0+1)*VP+rl1]=__float2bfloat16(v11);
            if(writeV){
                if(vr0<V){
                    g_v[(size_t)vr0*BN+b0+c0]=v00; g_v[(size_t)vr0*BN+b0+c0+1]=v01;
                    g_vh[(size_t)(b0+c0)*V+vr0]=__float2bfloat16(v00);
                    g_vh[(size_t)(b0+c0+1)*V+vr0]=__float2bfloat16(v01);
                }
                if(vr1<V){
                    g_v[(size_t)vr1*BN+b0+c0]=v10; g_v[(size_t)vr1*BN+b0+c0+1]=v11;
                    g_vh[(size_t)(b0+c0)*V+vr1]=__float2bfloat16(v10);
                    g_vh[(size_t)(b0+c0+1)*V+vr1]=__float2bfloat16(v11);
                }
            }
            float r0=v00+v10,r1=v01+v11;
            r0+=__shfl_xor_sync(~0u,r0,4); r0+=__shfl_xor_sync(~0u,r0,8); r0+=__shfl_xor_sync(~0u,r0,16);
            r1+=__shfl_xor_sync(~0u,r1,4); r1+=__shfl_xor_sync(~0u,r1,8); r1+=__shfl_xor_sync(~0u,r1,16);
            if(g==0){ atomicAdd(&W_s[c0],r0); atomicAdd(&W_s[c0+1],r1); }
        }
        __syncthreads();
        cp_ekv(sE,g_Ekv,v0,tid);
        __syncthreads();
        phB(sE,sV,w,lane,acc);
    }
    __syncthreads();
    if(tid<128){
        atomicAdd(&g_W[b0+tid],W_s[tid]);
        if(writeV) atomicAdd(&g_Wv[b0+tid],W_s[tid]);
    }
#pragma unroll
    for(int m=0;m<13;m++) for(int p=0;p<2;p++){
        int k=m*16+g,b=b0+w*16+p*8+2*tg;
        atomicAdd(&g_t[k*BN+b],acc[m][p][0]);
        atomicAdd(&g_t[k*BN+b+1],acc[m][p][1]);
        atomicAdd(&g_t[(k+8)*BN+b],acc[m][p][2]);
        atomicAdd(&g_t[(k+8)*BN+b+1],acc[m][p][3]);
    }
}

__global__ void uUpd(const float* __restrict__ theta){
    if(g_done) return;
    int b=blockIdx.x,k=threadIdx.x;
    __shared__ float red[256];
    float u=0.f;
    if(k<KT){ u=theta[b*KT+k]*INV_C/(g_W[b]+g_t[k*BN+b]); g_uf[k*BN+b]=u; }
    if(k<KS) g_ut[b*KS+k]=__float2bfloat16(u);
    if(k<KP) g_t[k*BN+b]=0.f;
    red[k]=u; __syncthreads();
    for(int s=128;s;s>>=1){ if(k<s) red[k]+=red[k+s]; __syncthreads(); }
    if(k==0){ g_U[b]=red[0]; g_W[b]=0.f; }
}

__global__ void resetWv(){
    if(g_done) return;
    int i=blockIdx.x*256+threadIdx.x;
    if(i<BN) g_Wv[i]=0.f;
}

__global__ __launch_bounds__(256) void errK(){
    if(g_done) return;
    extern __shared__ char sm[];
    char* sU=sm; char* sE=sm+55296; float* U_s=(float*)(sm+110592);
    int tid=threadIdx.x,lane=tid&31,w=tid>>5,g=lane>>2,tg=lane&3;
    int b0=blockIdx.y*128;
    cp_u(sU,b0,tid);
    if(tid<128) U_s[tid]=g_U[b0+tid];
    float err[16][2];
#pragma unroll
    for(int nt=0;nt<16;nt++){ err[nt][0]=0.f; err[nt][1]=0.f; }
    for(int t=blockIdx.x;t<NT;t+=GV){
        int v0=t*128;
        __syncthreads();
        cp_evk(sE,v0,tid);
        __syncthreads();
        float d[16][4];
#pragma unroll
        for(int nt=0;nt<16;nt++) for(int q=0;q<4;q++) d[nt][q]=0.f;
        phA(sE,sU,w,lane,d);
        int vr0=v0+w*16+g,vr1=vr0+8;
#pragma unroll
        for(int nt=0;nt<16;nt++){
            int c0=nt*8+2*tg;
            float Ua=U_s[c0],Ub=U_s[c0+1];
            if(vr0<V){
                float2 bw=*(const float2*)&g_bow[(size_t)vr0*BN+b0+c0];
                float2 vn=*(const float2*)&g_v[(size_t)vr0*BN+b0+c0];
                err[nt][0]+=fabsf(vn.x*(Ua+d[nt][0])-bw.x);
                err[nt][1]+=fabsf(vn.y*(Ub+d[nt][1])-bw.y);
            }
            if(vr1<V){
                float2 bw=*(const float2*)&g_bow[(size_t)vr1*BN+b0+c0];
                float2 vn=*(const float2*)&g_v[(size_t)vr1*BN+b0+c0];
                err[nt][0]+=fabsf(vn.x*(Ua+d[nt][2])-bw.x);
                err[nt][1]+=fabsf(vn.y*(Ub+d[nt][3])-bw.y);
            }
        }
    }
#pragma unroll
    for(int nt=0;nt<16;nt++){
        float r0=err[nt][0],r1=err[nt][1];
        r0+=__shfl_xor_sync(~0u,r0,4); r0+=__shfl_xor_sync(~0u,r0,8); r0+=__shfl_xor_sync(~0u,r0,16);
        r1+=__shfl_xor_sync(~0u,r1,4); r1+=__shfl_xor_sync(~0u,r1,8); r1+=__shfl_xor_sync(~0u,r1,16);
        if(g==0){
            atomicAdd(&g_errb[b0+nt*8+2*tg],r0);
            atomicAdd(&g_errb[b0+nt*8+2*tg+1],r1);
        }
    }
}

__global__ void doneK(){
    if(g_done) return;
    __shared__ float red[512];
    int t=threadIdx.x;
    red[t]=g_errb[t]; __syncthreads();
    for(int s=256;s;s>>=1){ if(t<s) red[t]=fmaxf(red[t],red[t+s]); __syncthreads(); }
    g_errb[t]=0.f;
    if(t==0&&red[0]<=THRESH_H) g_done=1;
}

__global__ __launch_bounds__(256) void finK(){
    extern __shared__ char sm[];
    char* sE=sm; char* sV=sm+56576;
    int tid=threadIdx.x,lane=tid&31,w=tid>>5,g=lane>>2,tg=lane&3;
    int b0=blockIdx.y*128;
    float acc[13][2][4];
#pragma unroll
    for(int m=0;m<13;m++) for(int p=0;p<2;p++) for(int q=0;q<4;q++) acc[m][p][q]=0.f;
    for(int t=blockIdx.x;t<NT;t+=GV){
        int v0=t*128;
        __syncthreads();
        cp_ekv(sE,g_Gkv,v0,tid);
        cp_vh(sV,b0,v0,tid);
        __syncthreads();
        phB(sE,sV,w,lane,acc);
    }
#pragma unroll
    for(int m=0;m<13;m++) for(int p=0;p<2;p++){
        int k=m*16+g,b=b0+w*16+p*8+2*tg;
        atomicAdd(&g_tf[k*BN+b],acc[m][p][0]);
        atomicAdd(&g_tf[k*BN+b+1],acc[m][p][1]);
        atomicAdd(&g_tf[(k+8)*BN+b],acc[m][p][2]);
        atomicAdd(&g_tf[(k+8)*BN+b+1],acc[m][p][3]);
    }
}

__global__ void divRed(float* __restrict__ out){
    __shared__ float red[1024];
    int t=threadIdx.x;
    float s=0.f;
    for(int i=t;i<KT*BN;i+=1024) s+=g_uf[i]*(g_Wv[i&511]+g_tf[i]);
    red[t]=s; __syncthreads();
    for(int st=512;st;st>>=1){ if(t<st) red[t]+=red[t+st]; __syncthreads(); }
    if(t==0) out[0]=red[0]*(C_NEG/512.f);
}

#define SZ_ITER 147712
#define SZ_ERR  111104
#define SZ_FIN  91392

extern "C" void kernel_launch(void* const* d_in, const int* in_sizes, int n_in,
                              void* d_out, int out_size) {
    const float* beta =(const float*)d_in[0];
    const float* theta=(const float*)d_in[1];
    const float* bow  =(const float*)d_in[2];
    float* out=(float*)d_out;

    cudaFuncSetAttribute(iterK,cudaFuncAttributeMaxDynamicSharedMemorySize,SZ_ITER);
    cudaFuncSetAttribute(errK, cudaFuncAttributeMaxDynamicSharedMemorySize,SZ_ERR);
    cudaFuncSetAttribute(finK, cudaFuncAttributeMaxDynamicSharedMemorySize,SZ_FIN);

    initK<<<432,256>>>();
    rowstats<<<512,256>>>(bow);
    bowT<<<dim3(1563,16),dim3(32,32)>>>(bow);
    kprep1<<<39063,256>>>(beta);
    kprep2<<<dim3(1563,7),dim3(32,32)>>>(beta);

    for(int blk=0;blk<5;blk++){
        for(int it=0;it<20;it++){
            iterK<<<dim3(GV,4),256,SZ_ITER>>>(0);
            uUpd<<<512,256>>>(theta);
        }
        resetWv<<<2,256>>>();
        iterK<<<dim3(GV,4),256,SZ_ITER>>>(1);
        uUpd<<<512,256>>>(theta);
        errK<<<dim3(GV,4),256,SZ_ERR>>>();
        doneK<<<1,512>>>();
    }
    finK<<<dim3(GV,4),256,SZ_FIN>>>();
    divRed<<<1,1024>>>(out);
}